// round 10
// baseline (speedup 1.0000x reference)
#include <cuda_runtime.h>
#include <math.h>

// Scratch for per-query MLP weights (N x cols). 4096*80 floats = 1.25 MB.
__device__ float g_weights[4096 * 80];

__device__ __forceinline__ void red_smem_add(unsigned int addr, float v) {
    asm volatile("red.shared.add.f32 [%0], %1;" :: "r"(addr), "f"(v) : "memory");
}

// ===========================================================================
// GEMM (fast path, dim=256, cols=65): weights = q @ Wg + bg.
// 300 CTAs x 512 threads (2 CTAs/SM -> 32 warps hiding the Wg LDG stream),
// 8 n per CTA, 16-way K-split: warp w owns d in [16w, 16w+16). Wg read from
// L2 (coalesced scalar LDGs, unroll-8). q transposed in smem. Partials
// tree-reduced (16-way) through smem.
// ===========================================================================
#define GSQ   0                    // sqT: 256 x 8           = 2048 floats
#define GPR   2048                 // partials: 16*8 x 66    = 8448 floats
#define GTOT  10496                // ~42 KB

__global__ void __launch_bounds__(512, 2)
posmlp_gemm512_kernel(const float* __restrict__ q,
                      const float* __restrict__ Wg,
                      const float* __restrict__ bg,
                      float* __restrict__ w_out) {
    extern __shared__ float sm[];
    const int n0   = blockIdx.x * 8;
    const int tid  = threadIdx.x;
    const int w    = tid >> 5;
    const int l    = tid & 31;

    // Stage q transposed: sqT[d*8 + nn] = q[(n0+nn)*256 + d].
    #pragma unroll
    for (int i = tid; i < 2048; i += 512) {
        const int nn = i >> 8;
        const int d  = i & 255;
        sm[GSQ + d * 8 + nn] = q[(size_t)n0 * 256 + i];
    }
    __syncthreads();

    const int d0 = w * 16;
    float2 acc[8];
    #pragma unroll
    for (int nn = 0; nn < 8; nn++) acc[nn] = make_float2(0.f, 0.f);
    float acc64[8];
    #pragma unroll
    for (int nn = 0; nn < 8; nn++) acc64[nn] = 0.f;

    #pragma unroll
    for (int db = 0; db < 16; db += 8) {
        float wpx[8], wpy[8], w64[8];
        #pragma unroll
        for (int j = 0; j < 8; j++) {
            const size_t base = (size_t)(d0 + db + j) * 65;
            wpx[j] = Wg[base + 2 * l];
            wpy[j] = Wg[base + 2 * l + 1];
            w64[j] = Wg[base + 64];
        }
        #pragma unroll
        for (int j = 0; j < 8; j++) {
            const int d = d0 + db + j;
            const float4 qa = *reinterpret_cast<const float4*>(&sm[GSQ + d * 8 + 0]);
            const float4 qb = *reinterpret_cast<const float4*>(&sm[GSQ + d * 8 + 4]);
            const float qv[8] = {qa.x, qa.y, qa.z, qa.w, qb.x, qb.y, qb.z, qb.w};
            #pragma unroll
            for (int nn = 0; nn < 8; nn++) {
                acc[nn].x = fmaf(qv[nn], wpx[j], acc[nn].x);
                acc[nn].y = fmaf(qv[nn], wpy[j], acc[nn].y);
            }
            if (l == 0) {
                #pragma unroll
                for (int nn = 0; nn < 8; nn++)
                    acc64[nn] = fmaf(qv[nn], w64[j], acc64[nn]);
            }
        }
    }

    #pragma unroll
    for (int nn = 0; nn < 8; nn++) {
        *reinterpret_cast<float2*>(&sm[GPR + (w * 8 + nn) * 66 + 2 * l]) = acc[nn];
    }
    if (l == 0) {
        #pragma unroll
        for (int nn = 0; nn < 8; nn++) sm[GPR + (w * 8 + nn) * 66 + 64] = acc64[nn];
    }
    __syncthreads();

    for (int o = tid; o < 520; o += 512) {
        const int nn = o / 65;
        const int c  = o - nn * 65;
        float s = 0.f;
        #pragma unroll
        for (int w16 = 0; w16 < 16; w16++) s += sm[GPR + (w16 * 8 + nn) * 66 + c];
        w_out[(size_t)(n0 + nn) * 65 + c] = s + bg[c];
    }
}

// ===========================================================================
// Main kernel (H=W=64, hidden=16): breakpoint/prefix sweep, v4 (branch-free).
// One CTA per n, 256 threads; thread t: row y=t>>2, 16 px at 16*(t&3).
// Table per unit: {e0 = w0*tx + b1, w1, sa = w2*|s|, inv = 1/s}.
// Scatter per unit is STRAIGHT-LINE: compute c, u=c*inv, sb=sa*u, bin index
// (clamped floor), A0/B0 via select+add, and TWO red.shared.add.f32 into the
// thread-private bins column — out-of-window units land in trash slot 0.
// No if(), no LDS round-trip, no BSSY. Clean warps skip the sweep LDS.
// ===========================================================================
__global__ void __launch_bounds__(256)
posmlp_bp16_kernel(const float* __restrict__ pos,
                   const float* __restrict__ wts,
                   float* __restrict__ out) {
    __shared__ float  sw[65];
    __shared__ float4 tab[16];
    __shared__ float2 bins[16 * 256];   // slot 0 = trash; slots 1..15 live

    const int n   = blockIdx.x;
    const int tid = threadIdx.x;

    if (tid < 65) sw[tid] = wts[(size_t)n * 65 + tid];
    const float4 p = *reinterpret_cast<const float4*>(&pos[(size_t)n * 4]);
    const float inv_bw = 1.0f / p.z;
    const float inv_bh = 1.0f / p.w;
    const float sx = inv_bw * (1.0f / 64.0f);
    const float tx = (0.5f * (1.0f / 64.0f) - p.x) * inv_bw;
    __syncthreads();

    if (tid < 16) {
        const int k = tid;
        const float w0 = sw[k];
        const float w2 = sw[48 + k];
        float s = w0 * sx;
        float sa, inv;
        if (fabsf(s) < 1e-18f) {
            const float sgn = (s >= 0.f) ? 1.0f : -1.0f;
            sa  = w2 * 1e-30f;
            inv = sgn * 1e30f;
        } else {
            sa  = w2 * fabsf(s);
            inv = __fdividef(1.0f, s);
        }
        tab[k] = make_float4(fmaf(w0, tx, sw[32 + k]), sw[16 + k], sa, inv);
    }
    // Zero bins via float4 (16*256*8B = 32 KB -> 2048 float4).
    {
        float4* b4 = reinterpret_cast<float4*>(bins);
        #pragma unroll
        for (int i = 0; i < 8; i++)
            b4[tid + i * 256] = make_float4(0.f, 0.f, 0.f, 0.f);
    }
    __syncthreads();

    const int y  = tid >> 2;
    const int qd = tid & 3;
    const float Lf = (float)(16 * qd);

    const float rel_y = (((float)y + 0.5f) * (1.0f / 64.0f) - p.y) * inv_bh;

    const unsigned int binbase =
        (unsigned int)__cvta_generic_to_shared(&bins[tid]);

    float A0 = 0.f;
    float B0 = sw[64];
    int   anyin = 0;

    #pragma unroll
    for (int k = 0; k < 16; k++) {
        const float4 T = tab[k];             // e0, w1, sa, inv
        const float c  = fmaf(rel_y, T.y, T.x);
        const float u  = c * T.w;            // c/s  (= -breakpoint_global_x)
        const float sb = T.z * u;            // sigma*beta
        float v = u + Lf;
        v = fminf(fmaxf(v, -16.5f), 0.5f);
        int bl = -__float2int_rd(v);
        bl = min(bl, 16);

        const bool neg   = (T.w < 0.f);
        const bool add0  = neg ? (bl > 0) : (bl == 0);
        const float alpha = neg ? -T.z : T.z;
        const float beta  = neg ? -sb  : sb;
        A0 += add0 ? alpha : 0.f;
        B0 += add0 ? beta  : 0.f;

        const bool inw = (unsigned)(bl - 1) < 15u;
        const int slot = inw ? bl : 0;
        anyin |= (int)inw;
        const unsigned int a = binbase + (unsigned int)slot * 2048u; // 256*8B
        red_smem_add(a,     T.z);   // sigma*alpha
        red_smem_add(a + 4, sb);    // sigma*beta
    }

    float* orow = out + (((size_t)n * 64 + y) * 64 + qd * 16);

    if (__all_sync(0xffffffffu, anyin == 0)) {
        // Clean warp: single linear function across the window.
        #pragma unroll
        for (int xi = 0; xi < 16; xi += 4) {
            float4 res;
            res.x = fmaf(A0, Lf + (float)(xi + 0), B0);
            res.y = fmaf(A0, Lf + (float)(xi + 1), B0);
            res.z = fmaf(A0, Lf + (float)(xi + 2), B0);
            res.w = fmaf(A0, Lf + (float)(xi + 3), B0);
            *reinterpret_cast<float4*>(orow + xi) = res;
        }
    } else {
        float A = A0, B = B0;
        #pragma unroll
        for (int xi = 0; xi < 16; xi += 4) {
            float4 res;
            float* rp = &res.x;
            #pragma unroll
            for (int j = 0; j < 4; j++) {
                const int slot = xi + j;
                if (slot > 0) {   // compile-time condition (full unroll)
                    const float2 d = bins[slot * 256 + tid];
                    A += d.x;
                    B += d.y;
                }
                rp[j] = fmaf(A, Lf + (float)slot, B);
            }
            *reinterpret_cast<float4*>(orow + xi) = res;
        }
    }
}

// ===========================================================================
// Fallback path (other shapes).
// ===========================================================================
__global__ void posmlp_gemm_kernel(const float* __restrict__ q,
                                   const float* __restrict__ Wg,
                                   const float* __restrict__ bg,
                                   float* __restrict__ w_out,
                                   int dim, int cols) {
    extern __shared__ float sqf[];
    const int n = blockIdx.x;
    const float* qr = q + (size_t)n * dim;
    for (int d = threadIdx.x; d < dim; d += blockDim.x) sqf[d] = qr[d];
    __syncthreads();
    for (int j = threadIdx.x; j < cols; j += blockDim.x) {
        float acc = bg[j];
        #pragma unroll 8
        for (int d = 0; d < dim; d++) {
            acc = fmaf(sqf[d], Wg[(size_t)d * cols + j], acc);
        }
        w_out[(size_t)n * cols + j] = acc;
    }
}

__global__ void posmlp_generic_kernel(const float* __restrict__ pos,
                                      const float* __restrict__ wts,
                                      float* __restrict__ out,
                                      int H, int W, int h, int cols) {
    const int n = blockIdx.x;
    const float* w = wts + (size_t)n * cols;
    const float cx = pos[(size_t)n * 4 + 0];
    const float cy = pos[(size_t)n * 4 + 1];
    const float bw = pos[(size_t)n * 4 + 2];
    const float bh = pos[(size_t)n * 4 + 3];
    const float b2 = w[4 * h];
    const int total = H * W;
    for (int idx = threadIdx.x; idx < total; idx += blockDim.x) {
        const int yy = idx / W;
        const int xx = idx - yy * W;
        const float rel_x = (((float)xx + 0.5f) / (float)W - cx) / bw;
        const float rel_y = (((float)yy + 0.5f) / (float)H - cy) / bh;
        float acc = b2;
        for (int k = 0; k < h; k++) {
            float pre = fmaf(rel_x, w[k], fmaf(rel_y, w[h + k], w[2 * h + k]));
            acc = fmaf(fmaxf(pre, 0.0f), w[3 * h + k], acc);
        }
        out[(size_t)n * total + idx] = acc;
    }
}

extern "C" void kernel_launch(void* const* d_in, const int* in_sizes, int n_in,
                              void* d_out, int out_size) {
    const float* pos = (const float*)d_in[0];
    const float* q   = (const float*)d_in[1];
    const float* Wg  = (const float*)d_in[2];
    const float* bg  = (const float*)d_in[3];
    float* out = (float*)d_out;

    const int N    = in_sizes[0] / 4;          // rows of pos
    const int dim  = in_sizes[1] / N;          // query dim
    const int cols = in_sizes[3];              // 4*h + 1
    const int HW   = out_size / N;
    const int H    = (int)(sqrt((double)HW) + 0.5);
    const int h    = (cols - 1) / 4;

    float* w_scratch;
    cudaGetSymbolAddress((void**)&w_scratch, g_weights);

    if (H == 64 && h == 16 && cols == 65 && dim == 256 && (N % 8) == 0) {
        const int smem_bytes = GTOT * sizeof(float);  // ~42 KB
        cudaFuncSetAttribute(posmlp_gemm512_kernel,
                             cudaFuncAttributeMaxDynamicSharedMemorySize, smem_bytes);
        posmlp_gemm512_kernel<<<N / 8, 512, smem_bytes>>>(q, Wg, bg, w_scratch);
        posmlp_bp16_kernel<<<N, 256>>>(pos, w_scratch, out);
    } else {
        posmlp_gemm_kernel<<<N, 256, dim * sizeof(float)>>>(q, Wg, bg, w_scratch, dim, cols);
        posmlp_generic_kernel<<<N, 256>>>(pos, w_scratch, out, H, H, h, cols);
    }
}

// round 11
// speedup vs baseline: 1.3813x; 1.3813x over previous
#include <cuda_runtime.h>
#include <math.h>

// Scratch for per-query MLP weights (N x cols). 4096*80 floats = 1.25 MB.
__device__ float g_weights[4096 * 80];

// ---------------------------------------------------------------------------
// f32x2 packed helpers (sm_100+)
// ---------------------------------------------------------------------------
__device__ __forceinline__ unsigned long long pack2(float lo, float hi) {
    unsigned long long r;
    asm("mov.b64 %0, {%1, %2};" : "=l"(r) : "f"(lo), "f"(hi));
    return r;
}

// acc = |x2*w10 + ay| * w2h
__device__ __forceinline__ void fma2_abs_init(unsigned long long& acc,
                                              unsigned long long x2,
                                              unsigned long long w10,
                                              unsigned long long ay,
                                              unsigned long long w2h) {
    asm("{\n\t"
        ".reg .b32 lo, hi;\n\t"
        ".reg .b64 p, r;\n\t"
        "fma.rn.f32x2 p, %1, %2, %3;\n\t"
        "mov.b64 {lo, hi}, p;\n\t"
        "abs.f32 lo, lo;\n\t"
        "abs.f32 hi, hi;\n\t"
        "mov.b64 r, {lo, hi};\n\t"
        "mul.rn.f32x2 %0, r, %4;\n\t"
        "}"
        : "=l"(acc)
        : "l"(x2), "l"(w10), "l"(ay), "l"(w2h));
}

// acc += |x2*w10 + ay| * w2h
__device__ __forceinline__ void fma2_abs_acc(unsigned long long& acc,
                                             unsigned long long x2,
                                             unsigned long long w10,
                                             unsigned long long ay,
                                             unsigned long long w2h) {
    asm("{\n\t"
        ".reg .b32 lo, hi;\n\t"
        ".reg .b64 p, r;\n\t"
        "fma.rn.f32x2 p, %1, %2, %3;\n\t"
        "mov.b64 {lo, hi}, p;\n\t"
        "abs.f32 lo, lo;\n\t"
        "abs.f32 hi, hi;\n\t"
        "mov.b64 r, {lo, hi};\n\t"
        "fma.rn.f32x2 %0, r, %4, %0;\n\t"
        "}"
        : "+l"(acc)
        : "l"(x2), "l"(w10), "l"(ay), "l"(w2h));
}

__device__ __forceinline__ void unpack2(unsigned long long v, float& lo, float& hi) {
    asm("mov.b64 {%0, %1}, %2;" : "=f"(lo), "=f"(hi) : "l"(v));
}

// ===========================================================================
// GEMM (fast path, dim=256, cols=65): weights = q @ Wg + bg.   (round-9 ver)
// 300 CTAs x 256 threads, 8 n per CTA. K-split: warp w owns d in [32w,32w+32).
// Wg read from L2 (coalesced scalar LDGs, unroll-8). q transposed in smem.
// Partials tree-reduced through smem.
// ===========================================================================
#define GSQ   0                    // sqT: 256 x 8          = 2048 floats
#define GPR   2048                 // partials: 8*8 x 66    = 4224 floats
#define GTOT  6272

__global__ void __launch_bounds__(256)
posmlp_gemm8_kernel(const float* __restrict__ q,
                    const float* __restrict__ Wg,
                    const float* __restrict__ bg,
                    float* __restrict__ w_out) {
    extern __shared__ float sm[];
    const int n0   = blockIdx.x * 8;
    const int tid  = threadIdx.x;
    const int w    = tid >> 5;
    const int l    = tid & 31;

    #pragma unroll
    for (int i = tid; i < 2048; i += 256) {
        const int nn = i >> 8;
        const int d  = i & 255;
        sm[GSQ + d * 8 + nn] = q[(size_t)n0 * 256 + i];
    }
    __syncthreads();

    const int d0 = w * 32;
    float2 acc[8];
    #pragma unroll
    for (int nn = 0; nn < 8; nn++) acc[nn] = make_float2(0.f, 0.f);
    float acc64[8];
    #pragma unroll
    for (int nn = 0; nn < 8; nn++) acc64[nn] = 0.f;

    #pragma unroll
    for (int db = 0; db < 32; db += 8) {
        float wpx[8], wpy[8], w64[8];
        #pragma unroll
        for (int j = 0; j < 8; j++) {
            const size_t base = (size_t)(d0 + db + j) * 65;
            wpx[j] = Wg[base + 2 * l];
            wpy[j] = Wg[base + 2 * l + 1];
            w64[j] = Wg[base + 64];
        }
        #pragma unroll
        for (int j = 0; j < 8; j++) {
            const int d = d0 + db + j;
            const float4 qa = *reinterpret_cast<const float4*>(&sm[GSQ + d * 8 + 0]);
            const float4 qb = *reinterpret_cast<const float4*>(&sm[GSQ + d * 8 + 4]);
            const float qv[8] = {qa.x, qa.y, qa.z, qa.w, qb.x, qb.y, qb.z, qb.w};
            #pragma unroll
            for (int nn = 0; nn < 8; nn++) {
                acc[nn].x = fmaf(qv[nn], wpx[j], acc[nn].x);
                acc[nn].y = fmaf(qv[nn], wpy[j], acc[nn].y);
            }
            if (l == 0) {
                #pragma unroll
                for (int nn = 0; nn < 8; nn++)
                    acc64[nn] = fmaf(qv[nn], w64[j], acc64[nn]);
            }
        }
    }

    #pragma unroll
    for (int nn = 0; nn < 8; nn++) {
        *reinterpret_cast<float2*>(&sm[GPR + (w * 8 + nn) * 66 + 2 * l]) = acc[nn];
    }
    if (l == 0) {
        #pragma unroll
        for (int nn = 0; nn < 8; nn++) sm[GPR + (w * 8 + nn) * 66 + 64] = acc64[nn];
    }
    __syncthreads();

    for (int o = tid; o < 520; o += 256) {
        const int nn = o / 65;
        const int c  = o - nn * 65;
        float s = 0.f;
        #pragma unroll
        for (int w8 = 0; w8 < 8; w8++) s += sm[GPR + (w8 * 8 + nn) * 66 + c];
        w_out[(size_t)(n0 + nn) * 65 + c] = s + bg[c];
    }
}

// ===========================================================================
// Main kernel (H=W=64, hidden=16): FFMA2-abs, ILP-8.
// One CTA per n, 256 threads; thread t: row y=t>>2, 16 px at 16*(t&3),
// processed as 2 batches of 8 INDEPENDENT pixel chains (in-flight FFMA2
// per SMSP ~32 -> hides the fma latency that capped round 5 at 50% pipe).
// relu(p)*w2 = 0.5*p*w2 + 0.5*|p|*w2; linear half folded into (LA, LBb2).
// All 24 weight pairs register-resident (launch_bounds(256,2): ~128 regs).
// ===========================================================================
__global__ void __launch_bounds__(256, 2)
posmlp_main64_kernel(const float* __restrict__ pos,
                     const float* __restrict__ wts,
                     float* __restrict__ out) {
    const int n   = blockIdx.x;
    const int tid = threadIdx.x;

    __shared__ float sw[65];
    if (tid < 65) sw[tid] = wts[(size_t)n * 65 + tid];
    __syncthreads();

    const float4 p = *reinterpret_cast<const float4*>(&pos[(size_t)n * 4]);
    const float inv_bw = 1.0f / p.z;
    const float inv_bh = 1.0f / p.w;

    const int y  = tid >> 2;
    const int x0 = (tid & 3) * 16;

    const float rel_y = (((float)y + 0.5f) * (1.0f / 64.0f) - p.y) * inv_bh;

    unsigned long long w10p[8], ayp[8], w2hp[8];
    float LA = 0.f, LB = 0.f;
    #pragma unroll
    for (int k2 = 0; k2 < 8; k2++) {
        const int k = 2 * k2;
        const float w0 = sw[k],     w1 = sw[k + 1];
        const float a0 = fmaf(rel_y, sw[16 + k],     sw[32 + k]);
        const float a1 = fmaf(rel_y, sw[16 + k + 1], sw[32 + k + 1]);
        const float h0 = 0.5f * sw[48 + k];
        const float h1 = 0.5f * sw[48 + k + 1];
        LA = fmaf(w0, h0, LA); LA = fmaf(w1, h1, LA);
        LB = fmaf(a0, h0, LB); LB = fmaf(a1, h1, LB);
        w10p[k2] = pack2(w0, w1);
        ayp[k2]  = pack2(a0, a1);
        w2hp[k2] = pack2(h0, h1);
    }
    const float LBb2 = LB + sw[64];

    const float sx = inv_bw * (1.0f / 64.0f);
    const float tx = (0.5f * (1.0f / 64.0f) - p.x) * inv_bw;

    float* orow = out + (((size_t)n * 64 + y) * 64 + x0);

    #pragma unroll
    for (int batch = 0; batch < 2; batch++) {
        const int xb = x0 + batch * 8;

        // 8 independent packed rel_x values
        float rx[8];
        unsigned long long x2[8];
        #pragma unroll
        for (int j = 0; j < 8; j++) {
            rx[j] = fmaf((float)(xb + j), sx, tx);
            x2[j] = pack2(rx[j], rx[j]);
        }

        // 8 independent accumulator chains
        unsigned long long acc[8];
        #pragma unroll
        for (int j = 0; j < 8; j++)
            fma2_abs_init(acc[j], x2[j], w10p[0], ayp[0], w2hp[0]);
        #pragma unroll
        for (int k2 = 1; k2 < 8; k2++) {
            #pragma unroll
            for (int j = 0; j < 8; j++)
                fma2_abs_acc(acc[j], x2[j], w10p[k2], ayp[k2], w2hp[k2]);
        }

        // Epilogue: hsum + linear half; two float4 stores.
        float res[8];
        #pragma unroll
        for (int j = 0; j < 8; j++) {
            float lo, hi;
            unpack2(acc[j], lo, hi);
            res[j] = (lo + hi) + fmaf(rx[j], LA, LBb2);
        }
        float4 v0 = make_float4(res[0], res[1], res[2], res[3]);
        float4 v1 = make_float4(res[4], res[5], res[6], res[7]);
        *reinterpret_cast<float4*>(orow + batch * 8)     = v0;
        *reinterpret_cast<float4*>(orow + batch * 8 + 4) = v1;
    }
}

// ===========================================================================
// Fallback path (other shapes).
// ===========================================================================
__global__ void posmlp_gemm_kernel(const float* __restrict__ q,
                                   const float* __restrict__ Wg,
                                   const float* __restrict__ bg,
                                   float* __restrict__ w_out,
                                   int dim, int cols) {
    extern __shared__ float sqf[];
    const int n = blockIdx.x;
    const float* qr = q + (size_t)n * dim;
    for (int d = threadIdx.x; d < dim; d += blockDim.x) sqf[d] = qr[d];
    __syncthreads();
    for (int j = threadIdx.x; j < cols; j += blockDim.x) {
        float acc = bg[j];
        #pragma unroll 8
        for (int d = 0; d < dim; d++) {
            acc = fmaf(sqf[d], Wg[(size_t)d * cols + j], acc);
        }
        w_out[(size_t)n * cols + j] = acc;
    }
}

__global__ void posmlp_generic_kernel(const float* __restrict__ pos,
                                      const float* __restrict__ wts,
                                      float* __restrict__ out,
                                      int H, int W, int h, int cols) {
    const int n = blockIdx.x;
    const float* w = wts + (size_t)n * cols;
    const float cx = pos[(size_t)n * 4 + 0];
    const float cy = pos[(size_t)n * 4 + 1];
    const float bw = pos[(size_t)n * 4 + 2];
    const float bh = pos[(size_t)n * 4 + 3];
    const float b2 = w[4 * h];
    const int total = H * W;
    for (int idx = threadIdx.x; idx < total; idx += blockDim.x) {
        const int yy = idx / W;
        const int xx = idx - yy * W;
        const float rel_x = (((float)xx + 0.5f) / (float)W - cx) / bw;
        const float rel_y = (((float)yy + 0.5f) / (float)H - cy) / bh;
        float acc = b2;
        for (int k = 0; k < h; k++) {
            float pre = fmaf(rel_x, w[k], fmaf(rel_y, w[h + k], w[2 * h + k]));
            acc = fmaf(fmaxf(pre, 0.0f), w[3 * h + k], acc);
        }
        out[(size_t)n * total + idx] = acc;
    }
}

extern "C" void kernel_launch(void* const* d_in, const int* in_sizes, int n_in,
                              void* d_out, int out_size) {
    const float* pos = (const float*)d_in[0];
    const float* q   = (const float*)d_in[1];
    const float* Wg  = (const float*)d_in[2];
    const float* bg  = (const float*)d_in[3];
    float* out = (float*)d_out;

    const int N    = in_sizes[0] / 4;          // rows of pos
    const int dim  = in_sizes[1] / N;          // query dim
    const int cols = in_sizes[3];              // 4*h + 1
    const int HW   = out_size / N;
    const int H    = (int)(sqrt((double)HW) + 0.5);
    const int h    = (cols - 1) / 4;

    float* w_scratch;
    cudaGetSymbolAddress((void**)&w_scratch, g_weights);

    if (H == 64 && h == 16 && cols == 65 && dim == 256 && (N % 8) == 0) {
        const int smem_bytes = GTOT * sizeof(float);  // ~25 KB
        cudaFuncSetAttribute(posmlp_gemm8_kernel,
                             cudaFuncAttributeMaxDynamicSharedMemorySize, smem_bytes);
        posmlp_gemm8_kernel<<<N / 8, 256, smem_bytes>>>(q, Wg, bg, w_scratch);
        posmlp_main64_kernel<<<N, 256>>>(pos, w_scratch, out);
    } else {
        posmlp_gemm_kernel<<<N, 256, dim * sizeof(float)>>>(q, Wg, bg, w_scratch, dim, cols);
        posmlp_generic_kernel<<<N, 256>>>(pos, w_scratch, out, H, H, h, cols);
    }
}

// round 12
// speedup vs baseline: 1.4286x; 1.0342x over previous
#include <cuda_runtime.h>
#include <math.h>

// Scratch for per-query MLP weights (N x cols). 4096*80 floats = 1.25 MB.
__device__ float g_weights[4096 * 80];

// ---------------------------------------------------------------------------
// f32x2 packed helpers (sm_100+)
// ---------------------------------------------------------------------------
__device__ __forceinline__ unsigned long long pack2(float lo, float hi) {
    unsigned long long r;
    asm("mov.b64 %0, {%1, %2};" : "=l"(r) : "f"(lo), "f"(hi));
    return r;
}

// acc = |x2*w10 + ay| * w2h
__device__ __forceinline__ void fma2_abs_init(unsigned long long& acc,
                                              unsigned long long x2,
                                              unsigned long long w10,
                                              unsigned long long ay,
                                              unsigned long long w2h) {
    asm("{\n\t"
        ".reg .b32 lo, hi;\n\t"
        ".reg .b64 p, r;\n\t"
        "fma.rn.f32x2 p, %1, %2, %3;\n\t"
        "mov.b64 {lo, hi}, p;\n\t"
        "abs.f32 lo, lo;\n\t"
        "abs.f32 hi, hi;\n\t"
        "mov.b64 r, {lo, hi};\n\t"
        "mul.rn.f32x2 %0, r, %4;\n\t"
        "}"
        : "=l"(acc)
        : "l"(x2), "l"(w10), "l"(ay), "l"(w2h));
}

// acc += |x2*w10 + ay| * w2h
__device__ __forceinline__ void fma2_abs_acc(unsigned long long& acc,
                                             unsigned long long x2,
                                             unsigned long long w10,
                                             unsigned long long ay,
                                             unsigned long long w2h) {
    asm("{\n\t"
        ".reg .b32 lo, hi;\n\t"
        ".reg .b64 p, r;\n\t"
        "fma.rn.f32x2 p, %1, %2, %3;\n\t"
        "mov.b64 {lo, hi}, p;\n\t"
        "abs.f32 lo, lo;\n\t"
        "abs.f32 hi, hi;\n\t"
        "mov.b64 r, {lo, hi};\n\t"
        "fma.rn.f32x2 %0, r, %4, %0;\n\t"
        "}"
        : "+l"(acc)
        : "l"(x2), "l"(w10), "l"(ay), "l"(w2h));
}

__device__ __forceinline__ void unpack2(unsigned long long v, float& lo, float& hi) {
    asm("mov.b64 {%0, %1}, %2;" : "=f"(lo), "=f"(hi) : "l"(v));
}

// ===========================================================================
// GEMM (fast path, dim=256, cols=65): weights = q @ Wg + bg.   (round-9 ver)
// ===========================================================================
#define GSQ   0                    // sqT: 256 x 8          = 2048 floats
#define GPR   2048                 // partials: 8*8 x 66    = 4224 floats
#define GTOT  6272

__global__ void __launch_bounds__(256)
posmlp_gemm8_kernel(const float* __restrict__ q,
                    const float* __restrict__ Wg,
                    const float* __restrict__ bg,
                    float* __restrict__ w_out) {
    extern __shared__ float sm[];
    const int n0   = blockIdx.x * 8;
    const int tid  = threadIdx.x;
    const int w    = tid >> 5;
    const int l    = tid & 31;

    #pragma unroll
    for (int i = tid; i < 2048; i += 256) {
        const int nn = i >> 8;
        const int d  = i & 255;
        sm[GSQ + d * 8 + nn] = q[(size_t)n0 * 256 + i];
    }
    __syncthreads();

    const int d0 = w * 32;
    float2 acc[8];
    #pragma unroll
    for (int nn = 0; nn < 8; nn++) acc[nn] = make_float2(0.f, 0.f);
    float acc64[8];
    #pragma unroll
    for (int nn = 0; nn < 8; nn++) acc64[nn] = 0.f;

    #pragma unroll
    for (int db = 0; db < 32; db += 8) {
        float wpx[8], wpy[8], w64[8];
        #pragma unroll
        for (int j = 0; j < 8; j++) {
            const size_t base = (size_t)(d0 + db + j) * 65;
            wpx[j] = Wg[base + 2 * l];
            wpy[j] = Wg[base + 2 * l + 1];
            w64[j] = Wg[base + 64];
        }
        #pragma unroll
        for (int j = 0; j < 8; j++) {
            const int d = d0 + db + j;
            const float4 qa = *reinterpret_cast<const float4*>(&sm[GSQ + d * 8 + 0]);
            const float4 qb = *reinterpret_cast<const float4*>(&sm[GSQ + d * 8 + 4]);
            const float qv[8] = {qa.x, qa.y, qa.z, qa.w, qb.x, qb.y, qb.z, qb.w};
            #pragma unroll
            for (int nn = 0; nn < 8; nn++) {
                acc[nn].x = fmaf(qv[nn], wpx[j], acc[nn].x);
                acc[nn].y = fmaf(qv[nn], wpy[j], acc[nn].y);
            }
            if (l == 0) {
                #pragma unroll
                for (int nn = 0; nn < 8; nn++)
                    acc64[nn] = fmaf(qv[nn], w64[j], acc64[nn]);
            }
        }
    }

    #pragma unroll
    for (int nn = 0; nn < 8; nn++) {
        *reinterpret_cast<float2*>(&sm[GPR + (w * 8 + nn) * 66 + 2 * l]) = acc[nn];
    }
    if (l == 0) {
        #pragma unroll
        for (int nn = 0; nn < 8; nn++) sm[GPR + (w * 8 + nn) * 66 + 64] = acc64[nn];
    }
    __syncthreads();

    for (int o = tid; o < 520; o += 256) {
        const int nn = o / 65;
        const int c  = o - nn * 65;
        float s = 0.f;
        #pragma unroll
        for (int w8 = 0; w8 < 8; w8++) s += sm[GPR + (w8 * 8 + nn) * 66 + c];
        w_out[(size_t)(n0 + nn) * 65 + c] = s + bg[c];
    }
}

// ===========================================================================
// Main kernel (H=W=64, hidden=16): FFMA2-abs ILP-8, 8 BOXES PER CTA.
// Grid = 300 CTAs (1.01 waves at 2 CTAs/SM — no wave quantization, prologue
// amortized 8x). 256 threads; thread t: row y=t>>2, 16 px at 16*(t&3).
// Weights for all 8 n loaded cooperatively into smem once; per-n register
// table build then the validated FFMA2-abs inner loop (2 batches x 8 chains).
// ===========================================================================
__global__ void __launch_bounds__(256, 2)
posmlp_main8_kernel(const float* __restrict__ pos,
                    const float* __restrict__ wts,
                    float* __restrict__ out) {
    const int n0  = blockIdx.x * 8;
    const int tid = threadIdx.x;

    __shared__ float  sw[8 * 68];   // stride 68: padding for bank spread
    __shared__ float4 spos[8];

    for (int i = tid; i < 520; i += 256) {
        const int nn = i / 65;
        const int c  = i - nn * 65;
        sw[nn * 68 + c] = wts[(size_t)n0 * 65 + i];
    }
    if (tid < 8)
        spos[tid] = *reinterpret_cast<const float4*>(&pos[(size_t)(n0 + tid) * 4]);
    __syncthreads();

    const int y  = tid >> 2;
    const int x0 = (tid & 3) * 16;
    const float yc = ((float)y + 0.5f) * (1.0f / 64.0f);

    for (int nn = 0; nn < 8; nn++) {
        const float* w = &sw[nn * 68];
        const float4 p = spos[nn];
        const float inv_bw = 1.0f / p.z;
        const float inv_bh = 1.0f / p.w;

        const float rel_y = (yc - p.y) * inv_bh;

        unsigned long long w10p[8], ayp[8], w2hp[8];
        float LA = 0.f, LB = 0.f;
        #pragma unroll
        for (int k2 = 0; k2 < 8; k2++) {
            const int k = 2 * k2;
            const float w0 = w[k],     w1 = w[k + 1];
            const float a0 = fmaf(rel_y, w[16 + k],     w[32 + k]);
            const float a1 = fmaf(rel_y, w[16 + k + 1], w[32 + k + 1]);
            const float h0 = 0.5f * w[48 + k];
            const float h1 = 0.5f * w[48 + k + 1];
            LA = fmaf(w0, h0, LA); LA = fmaf(w1, h1, LA);
            LB = fmaf(a0, h0, LB); LB = fmaf(a1, h1, LB);
            w10p[k2] = pack2(w0, w1);
            ayp[k2]  = pack2(a0, a1);
            w2hp[k2] = pack2(h0, h1);
        }
        const float LBb2 = LB + w[64];

        const float sx = inv_bw * (1.0f / 64.0f);
        const float tx = (0.5f * (1.0f / 64.0f) - p.x) * inv_bw;

        float* orow = out + (((size_t)(n0 + nn) * 64 + y) * 64 + x0);

        #pragma unroll
        for (int batch = 0; batch < 2; batch++) {
            const int xb = x0 + batch * 8;

            float rx[8];
            unsigned long long x2[8];
            #pragma unroll
            for (int j = 0; j < 8; j++) {
                rx[j] = fmaf((float)(xb + j), sx, tx);
                x2[j] = pack2(rx[j], rx[j]);
            }

            unsigned long long acc[8];
            #pragma unroll
            for (int j = 0; j < 8; j++)
                fma2_abs_init(acc[j], x2[j], w10p[0], ayp[0], w2hp[0]);
            #pragma unroll
            for (int k2 = 1; k2 < 8; k2++) {
                #pragma unroll
                for (int j = 0; j < 8; j++)
                    fma2_abs_acc(acc[j], x2[j], w10p[k2], ayp[k2], w2hp[k2]);
            }

            float res[8];
            #pragma unroll
            for (int j = 0; j < 8; j++) {
                float lo, hi;
                unpack2(acc[j], lo, hi);
                res[j] = (lo + hi) + fmaf(rx[j], LA, LBb2);
            }
            float4 v0 = make_float4(res[0], res[1], res[2], res[3]);
            float4 v1 = make_float4(res[4], res[5], res[6], res[7]);
            *reinterpret_cast<float4*>(orow + batch * 8)     = v0;
            *reinterpret_cast<float4*>(orow + batch * 8 + 4) = v1;
        }
    }
}

// ===========================================================================
// Fallback path (other shapes).
// ===========================================================================
__global__ void posmlp_gemm_kernel(const float* __restrict__ q,
                                   const float* __restrict__ Wg,
                                   const float* __restrict__ bg,
                                   float* __restrict__ w_out,
                                   int dim, int cols) {
    extern __shared__ float sqf[];
    const int n = blockIdx.x;
    const float* qr = q + (size_t)n * dim;
    for (int d = threadIdx.x; d < dim; d += blockDim.x) sqf[d] = qr[d];
    __syncthreads();
    for (int j = threadIdx.x; j < cols; j += blockDim.x) {
        float acc = bg[j];
        #pragma unroll 8
        for (int d = 0; d < dim; d++) {
            acc = fmaf(sqf[d], Wg[(size_t)d * cols + j], acc);
        }
        w_out[(size_t)n * cols + j] = acc;
    }
}

__global__ void posmlp_generic_kernel(const float* __restrict__ pos,
                                      const float* __restrict__ wts,
                                      float* __restrict__ out,
                                      int H, int W, int h, int cols) {
    const int n = blockIdx.x;
    const float* w = wts + (size_t)n * cols;
    const float cx = pos[(size_t)n * 4 + 0];
    const float cy = pos[(size_t)n * 4 + 1];
    const float bw = pos[(size_t)n * 4 + 2];
    const float bh = pos[(size_t)n * 4 + 3];
    const float b2 = w[4 * h];
    const int total = H * W;
    for (int idx = threadIdx.x; idx < total; idx += blockDim.x) {
        const int yy = idx / W;
        const int xx = idx - yy * W;
        const float rel_x = (((float)xx + 0.5f) / (float)W - cx) / bw;
        const float rel_y = (((float)yy + 0.5f) / (float)H - cy) / bh;
        float acc = b2;
        for (int k = 0; k < h; k++) {
            float pre = fmaf(rel_x, w[k], fmaf(rel_y, w[h + k], w[2 * h + k]));
            acc = fmaf(fmaxf(pre, 0.0f), w[3 * h + k], acc);
        }
        out[(size_t)n * total + idx] = acc;
    }
}

extern "C" void kernel_launch(void* const* d_in, const int* in_sizes, int n_in,
                              void* d_out, int out_size) {
    const float* pos = (const float*)d_in[0];
    const float* q   = (const float*)d_in[1];
    const float* Wg  = (const float*)d_in[2];
    const float* bg  = (const float*)d_in[3];
    float* out = (float*)d_out;

    const int N    = in_sizes[0] / 4;          // rows of pos
    const int dim  = in_sizes[1] / N;          // query dim
    const int cols = in_sizes[3];              // 4*h + 1
    const int HW   = out_size / N;
    const int H    = (int)(sqrt((double)HW) + 0.5);
    const int h    = (cols - 1) / 4;

    float* w_scratch;
    cudaGetSymbolAddress((void**)&w_scratch, g_weights);

    if (H == 64 && h == 16 && cols == 65 && dim == 256 && (N % 8) == 0) {
        const int smem_bytes = GTOT * sizeof(float);  // ~25 KB
        cudaFuncSetAttribute(posmlp_gemm8_kernel,
                             cudaFuncAttributeMaxDynamicSharedMemorySize, smem_bytes);
        posmlp_gemm8_kernel<<<N / 8, 256, smem_bytes>>>(q, Wg, bg, w_scratch);
        posmlp_main8_kernel<<<N / 8, 256>>>(pos, w_scratch, out);
    } else {
        posmlp_gemm_kernel<<<N, 256, dim * sizeof(float)>>>(q, Wg, bg, w_scratch, dim, cols);
        posmlp_generic_kernel<<<N, 256>>>(pos, w_scratch, out, H, H, h, cols);
    }
}

// round 13
// speedup vs baseline: 1.4904x; 1.0433x over previous
#include <cuda_runtime.h>
#include <math.h>

// Scratch for the fallback path only.
__device__ float g_weights[4096 * 80];

// ---------------------------------------------------------------------------
// f32x2 packed helpers (sm_100+)
// ---------------------------------------------------------------------------
__device__ __forceinline__ unsigned long long pack2(float lo, float hi) {
    unsigned long long r;
    asm("mov.b64 %0, {%1, %2};" : "=l"(r) : "f"(lo), "f"(hi));
    return r;
}

// acc = |x2*w10 + ay| * w2h
__device__ __forceinline__ void fma2_abs_init(unsigned long long& acc,
                                              unsigned long long x2,
                                              unsigned long long w10,
                                              unsigned long long ay,
                                              unsigned long long w2h) {
    asm("{\n\t"
        ".reg .b32 lo, hi;\n\t"
        ".reg .b64 p, r;\n\t"
        "fma.rn.f32x2 p, %1, %2, %3;\n\t"
        "mov.b64 {lo, hi}, p;\n\t"
        "abs.f32 lo, lo;\n\t"
        "abs.f32 hi, hi;\n\t"
        "mov.b64 r, {lo, hi};\n\t"
        "mul.rn.f32x2 %0, r, %4;\n\t"
        "}"
        : "=l"(acc)
        : "l"(x2), "l"(w10), "l"(ay), "l"(w2h));
}

// acc += |x2*w10 + ay| * w2h
__device__ __forceinline__ void fma2_abs_acc(unsigned long long& acc,
                                             unsigned long long x2,
                                             unsigned long long w10,
                                             unsigned long long ay,
                                             unsigned long long w2h) {
    asm("{\n\t"
        ".reg .b32 lo, hi;\n\t"
        ".reg .b64 p, r;\n\t"
        "fma.rn.f32x2 p, %1, %2, %3;\n\t"
        "mov.b64 {lo, hi}, p;\n\t"
        "abs.f32 lo, lo;\n\t"
        "abs.f32 hi, hi;\n\t"
        "mov.b64 r, {lo, hi};\n\t"
        "fma.rn.f32x2 %0, r, %4, %0;\n\t"
        "}"
        : "+l"(acc)
        : "l"(x2), "l"(w10), "l"(ay), "l"(w2h));
}

__device__ __forceinline__ void unpack2(unsigned long long v, float& lo, float& hi) {
    asm("mov.b64 {%0, %1}, %2;" : "=f"(lo), "=f"(hi) : "l"(v));
}

// ===========================================================================
// FUSED kernel (fast path, dim=256, cols=65, H=W=64, hidden=16).
// Grid = N/8 CTAs x 256 threads, launch_bounds(256,2).
// Phase 1 (GEMM): weights for THIS CTA's 8 queries computed into smem
//   (k-split across 8 warps, partial-reduce; Wg streamed coalesced from L2;
//   q transposed in smem). No global scratch, no second launch.
// Phase 2 (pixels): validated FFMA2-abs inner loop, ILP-8, 2 batches,
//   float4 stores. Per-CTA GEMM latency is hidden by the co-resident CTA's
//   phase-2 FMA stream.
// ===========================================================================
#define FSQ   0                    // sqT: 256 x 8          = 2048 floats
#define FPR   2048                 // partials: 8*8 x 66    = 4224 floats
#define FSW   6272                 // weights: 8 x 68       = 544 floats
#define FTOT  6816                 // ~27 KB

__global__ void __launch_bounds__(256, 2)
posmlp_fused8_kernel(const float* __restrict__ pos,
                     const float* __restrict__ q,
                     const float* __restrict__ Wg,
                     const float* __restrict__ bg,
                     float* __restrict__ out) {
    extern __shared__ float sm[];
    __shared__ float4 spos[8];

    const int n0  = blockIdx.x * 8;
    const int tid = threadIdx.x;
    const int w   = tid >> 5;
    const int l   = tid & 31;

    // ---- Phase 1: GEMM into smem ----
    #pragma unroll
    for (int i = tid; i < 2048; i += 256) {
        const int nn = i >> 8;
        const int d  = i & 255;
        sm[FSQ + d * 8 + nn] = q[(size_t)n0 * 256 + i];
    }
    if (tid < 8)
        spos[tid] = *reinterpret_cast<const float4*>(&pos[(size_t)(n0 + tid) * 4]);
    __syncthreads();

    {
        const int d0 = w * 32;
        float2 acc[8];
        #pragma unroll
        for (int nn = 0; nn < 8; nn++) acc[nn] = make_float2(0.f, 0.f);
        float acc64[8];
        #pragma unroll
        for (int nn = 0; nn < 8; nn++) acc64[nn] = 0.f;

        #pragma unroll
        for (int db = 0; db < 32; db += 8) {
            float wpx[8], wpy[8], w64[8];
            #pragma unroll
            for (int j = 0; j < 8; j++) {
                const size_t base = (size_t)(d0 + db + j) * 65;
                wpx[j] = Wg[base + 2 * l];
                wpy[j] = Wg[base + 2 * l + 1];
                w64[j] = Wg[base + 64];
            }
            #pragma unroll
            for (int j = 0; j < 8; j++) {
                const int d = d0 + db + j;
                const float4 qa = *reinterpret_cast<const float4*>(&sm[FSQ + d * 8 + 0]);
                const float4 qb = *reinterpret_cast<const float4*>(&sm[FSQ + d * 8 + 4]);
                const float qv[8] = {qa.x, qa.y, qa.z, qa.w, qb.x, qb.y, qb.z, qb.w};
                #pragma unroll
                for (int nn = 0; nn < 8; nn++) {
                    acc[nn].x = fmaf(qv[nn], wpx[j], acc[nn].x);
                    acc[nn].y = fmaf(qv[nn], wpy[j], acc[nn].y);
                }
                if (l == 0) {
                    #pragma unroll
                    for (int nn = 0; nn < 8; nn++)
                        acc64[nn] = fmaf(qv[nn], w64[j], acc64[nn]);
                }
            }
        }

        __syncthreads();   // sqT no longer needed; FPR region reuses it? (separate region, safe anyway)

        #pragma unroll
        for (int nn = 0; nn < 8; nn++) {
            *reinterpret_cast<float2*>(&sm[FPR + (w * 8 + nn) * 66 + 2 * l]) = acc[nn];
        }
        if (l == 0) {
            #pragma unroll
            for (int nn = 0; nn < 8; nn++) sm[FPR + (w * 8 + nn) * 66 + 64] = acc64[nn];
        }
        __syncthreads();

        for (int o = tid; o < 520; o += 256) {
            const int nn = o / 65;
            const int c  = o - nn * 65;
            float s = 0.f;
            #pragma unroll
            for (int w8 = 0; w8 < 8; w8++) s += sm[FPR + (w8 * 8 + nn) * 66 + c];
            sm[FSW + nn * 68 + c] = s + bg[c];
        }
    }
    __syncthreads();

    // ---- Phase 2: pixel evaluation (FFMA2-abs, ILP-8) ----
    const int y  = tid >> 2;
    const int x0 = (tid & 3) * 16;
    const float yc = ((float)y + 0.5f) * (1.0f / 64.0f);

    for (int nn = 0; nn < 8; nn++) {
        const float* wv = &sm[FSW + nn * 68];
        const float4 p = spos[nn];
        const float inv_bw = 1.0f / p.z;
        const float inv_bh = 1.0f / p.w;

        const float rel_y = (yc - p.y) * inv_bh;

        unsigned long long w10p[8], ayp[8], w2hp[8];
        float LA = 0.f, LB = 0.f;
        #pragma unroll
        for (int k2 = 0; k2 < 8; k2++) {
            const int k = 2 * k2;
            const float w0 = wv[k],     w1 = wv[k + 1];
            const float a0 = fmaf(rel_y, wv[16 + k],     wv[32 + k]);
            const float a1 = fmaf(rel_y, wv[16 + k + 1], wv[32 + k + 1]);
            const float h0 = 0.5f * wv[48 + k];
            const float h1 = 0.5f * wv[48 + k + 1];
            LA = fmaf(w0, h0, LA); LA = fmaf(w1, h1, LA);
            LB = fmaf(a0, h0, LB); LB = fmaf(a1, h1, LB);
            w10p[k2] = pack2(w0, w1);
            ayp[k2]  = pack2(a0, a1);
            w2hp[k2] = pack2(h0, h1);
        }
        const float LBb2 = LB + wv[64];

        const float sx = inv_bw * (1.0f / 64.0f);
        const float tx = (0.5f * (1.0f / 64.0f) - p.x) * inv_bw;

        float* orow = out + (((size_t)(n0 + nn) * 64 + y) * 64 + x0);

        #pragma unroll
        for (int batch = 0; batch < 2; batch++) {
            const int xb = x0 + batch * 8;

            float rx[8];
            unsigned long long x2[8];
            #pragma unroll
            for (int j = 0; j < 8; j++) {
                rx[j] = fmaf((float)(xb + j), sx, tx);
                x2[j] = pack2(rx[j], rx[j]);
            }

            unsigned long long acc[8];
            #pragma unroll
            for (int j = 0; j < 8; j++)
                fma2_abs_init(acc[j], x2[j], w10p[0], ayp[0], w2hp[0]);
            #pragma unroll
            for (int k2 = 1; k2 < 8; k2++) {
                #pragma unroll
                for (int j = 0; j < 8; j++)
                    fma2_abs_acc(acc[j], x2[j], w10p[k2], ayp[k2], w2hp[k2]);
            }

            float res[8];
            #pragma unroll
            for (int j = 0; j < 8; j++) {
                float lo, hi;
                unpack2(acc[j], lo, hi);
                res[j] = (lo + hi) + fmaf(rx[j], LA, LBb2);
            }
            float4 v0 = make_float4(res[0], res[1], res[2], res[3]);
            float4 v1 = make_float4(res[4], res[5], res[6], res[7]);
            *reinterpret_cast<float4*>(orow + batch * 8)     = v0;
            *reinterpret_cast<float4*>(orow + batch * 8 + 4) = v1;
        }
    }
}

// ===========================================================================
// Fallback path (other shapes).
// ===========================================================================
__global__ void posmlp_gemm_kernel(const float* __restrict__ q,
                                   const float* __restrict__ Wg,
                                   const float* __restrict__ bg,
                                   float* __restrict__ w_out,
                                   int dim, int cols) {
    extern __shared__ float sqf[];
    const int n = blockIdx.x;
    const float* qr = q + (size_t)n * dim;
    for (int d = threadIdx.x; d < dim; d += blockDim.x) sqf[d] = qr[d];
    __syncthreads();
    for (int j = threadIdx.x; j < cols; j += blockDim.x) {
        float acc = bg[j];
        #pragma unroll 8
        for (int d = 0; d < dim; d++) {
            acc = fmaf(sqf[d], Wg[(size_t)d * cols + j], acc);
        }
        w_out[(size_t)n * cols + j] = acc;
    }
}

__global__ void posmlp_generic_kernel(const float* __restrict__ pos,
                                      const float* __restrict__ wts,
                                      float* __restrict__ out,
                                      int H, int W, int h, int cols) {
    const int n = blockIdx.x;
    const float* w = wts + (size_t)n * cols;
    const float cx = pos[(size_t)n * 4 + 0];
    const float cy = pos[(size_t)n * 4 + 1];
    const float bw = pos[(size_t)n * 4 + 2];
    const float bh = pos[(size_t)n * 4 + 3];
    const float b2 = w[4 * h];
    const int total = H * W;
    for (int idx = threadIdx.x; idx < total; idx += blockDim.x) {
        const int yy = idx / W;
        const int xx = idx - yy * W;
        const float rel_x = (((float)xx + 0.5f) / (float)W - cx) / bw;
        const float rel_y = (((float)yy + 0.5f) / (float)H - cy) / bh;
        float acc = b2;
        for (int k = 0; k < h; k++) {
            float pre = fmaf(rel_x, w[k], fmaf(rel_y, w[h + k], w[2 * h + k]));
            acc = fmaf(fmaxf(pre, 0.0f), w[3 * h + k], acc);
        }
        out[(size_t)n * total + idx] = acc;
    }
}

extern "C" void kernel_launch(void* const* d_in, const int* in_sizes, int n_in,
                              void* d_out, int out_size) {
    const float* pos = (const float*)d_in[0];
    const float* q   = (const float*)d_in[1];
    const float* Wg  = (const float*)d_in[2];
    const float* bg  = (const float*)d_in[3];
    float* out = (float*)d_out;

    const int N    = in_sizes[0] / 4;          // rows of pos
    const int dim  = in_sizes[1] / N;          // query dim
    const int cols = in_sizes[3];              // 4*h + 1
    const int HW   = out_size / N;
    const int H    = (int)(sqrt((double)HW) + 0.5);
    const int h    = (cols - 1) / 4;

    if (H == 64 && h == 16 && cols == 65 && dim == 256 && (N % 8) == 0) {
        const int smem_bytes = FTOT * sizeof(float);  // ~27 KB
        cudaFuncSetAttribute(posmlp_fused8_kernel,
                             cudaFuncAttributeMaxDynamicSharedMemorySize, smem_bytes);
        posmlp_fused8_kernel<<<N / 8, 256, smem_bytes>>>(pos, q, Wg, bg, out);
    } else {
        float* w_scratch;
        cudaGetSymbolAddress((void**)&w_scratch, g_weights);
        posmlp_gemm_kernel<<<N, 256, dim * sizeof(float)>>>(q, Wg, bg, w_scratch, dim, cols);
        posmlp_generic_kernel<<<N, 256>>>(pos, w_scratch, out, H, H, h, cols);
    }
}

// round 14
// speedup vs baseline: 1.4943x; 1.0026x over previous
#include <cuda_runtime.h>
#include <math.h>

typedef unsigned long long u64;

// Scratch for the fallback path only.
__device__ float g_weights[4096 * 80];

// ---------------------------------------------------------------------------
// f32x2 packed helpers (sm_100+)
// ---------------------------------------------------------------------------
__device__ __forceinline__ u64 pack2(float lo, float hi) {
    u64 r;
    asm("mov.b64 %0, {%1, %2};" : "=l"(r) : "f"(lo), "f"(hi));
    return r;
}

__device__ __forceinline__ void unpack2(u64 v, float& lo, float& hi) {
    asm("mov.b64 {%0, %1}, %2;" : "=f"(lo), "=f"(hi) : "l"(v));
}

// acc = |x2*w10 + ay| * w2h
__device__ __forceinline__ void fma2_abs_init(u64& acc, u64 x2, u64 w10,
                                              u64 ay, u64 w2h) {
    asm("{\n\t"
        ".reg .b32 lo, hi;\n\t"
        ".reg .b64 p, r;\n\t"
        "fma.rn.f32x2 p, %1, %2, %3;\n\t"
        "mov.b64 {lo, hi}, p;\n\t"
        "abs.f32 lo, lo;\n\t"
        "abs.f32 hi, hi;\n\t"
        "mov.b64 r, {lo, hi};\n\t"
        "mul.rn.f32x2 %0, r, %4;\n\t"
        "}"
        : "=l"(acc)
        : "l"(x2), "l"(w10), "l"(ay), "l"(w2h));
}

// acc += |x2*w10 + ay| * w2h
__device__ __forceinline__ void fma2_abs_acc(u64& acc, u64 x2, u64 w10,
                                             u64 ay, u64 w2h) {
    asm("{\n\t"
        ".reg .b32 lo, hi;\n\t"
        ".reg .b64 p, r;\n\t"
        "fma.rn.f32x2 p, %1, %2, %3;\n\t"
        "mov.b64 {lo, hi}, p;\n\t"
        "abs.f32 lo, lo;\n\t"
        "abs.f32 hi, hi;\n\t"
        "mov.b64 r, {lo, hi};\n\t"
        "fma.rn.f32x2 %0, r, %4, %0;\n\t"
        "}"
        : "+l"(acc)
        : "l"(x2), "l"(w10), "l"(ay), "l"(w2h));
}

// ===========================================================================
// FUSED kernel (fast path, dim=256, cols=65, H=W=64, hidden=16).
// Grid = N/4 CTAs x 256 threads, launch_bounds(256,3): 4 boxes per CTA,
// 600 CTAs = 1.35 waves at 3 CTAs/SM (24 warps/SM resident).
// Phase 1: GEMM for 4 queries into smem (k-split, partial-reduce).
// Tables (w10, w2h, w1, b1 packed pairs) live in SMEM as u64 — broadcast
// LDS.64 in the inner loop; only ayp (rel_y-dependent) is per-thread regs.
// Phase 2: FFMA2-abs inner loop, ILP-8, float4 stores.
// ===========================================================================
#define FSQ   0                    // sqT: 256 x 4              = 1024 floats
#define FPR   1024                 // partials: 8*4 x 66        = 2112 floats
#define FSW   3136                 // weights: 4 x 68           = 272 floats
#define FTAB  3408                 // 4 u64 tables x 32 entries = 256 floats
#define FLA   3664                 // LA per box                = 4 floats
#define FTOT  3672                 // ~14.7 KB

__global__ void __launch_bounds__(256, 3)
posmlp_fused4_kernel(const float* __restrict__ pos,
                     const float* __restrict__ q,
                     const float* __restrict__ Wg,
                     const float* __restrict__ bg,
                     float* __restrict__ out) {
    extern __shared__ float sm[];
    __shared__ float4 spos[4];

    const int n0  = blockIdx.x * 4;
    const int tid = threadIdx.x;
    const int w   = tid >> 5;
    const int l   = tid & 31;

    // ---- Phase 1: GEMM into smem ----
    #pragma unroll
    for (int i = tid; i < 1024; i += 256) {
        const int nn = i >> 8;
        const int d  = i & 255;
        sm[FSQ + d * 4 + nn] = q[(size_t)n0 * 256 + i];
    }
    if (tid < 4)
        spos[tid] = *reinterpret_cast<const float4*>(&pos[(size_t)(n0 + tid) * 4]);
    __syncthreads();

    {
        const int d0 = w * 32;
        float2 acc[4];
        #pragma unroll
        for (int nn = 0; nn < 4; nn++) acc[nn] = make_float2(0.f, 0.f);
        float acc64[4] = {0.f, 0.f, 0.f, 0.f};

        #pragma unroll
        for (int db = 0; db < 32; db += 8) {
            float wpx[8], wpy[8], w64[8];
            #pragma unroll
            for (int j = 0; j < 8; j++) {
                const size_t base = (size_t)(d0 + db + j) * 65;
                wpx[j] = Wg[base + 2 * l];
                wpy[j] = Wg[base + 2 * l + 1];
                w64[j] = Wg[base + 64];
            }
            #pragma unroll
            for (int j = 0; j < 8; j++) {
                const int d = d0 + db + j;
                const float4 qa = *reinterpret_cast<const float4*>(&sm[FSQ + d * 4]);
                const float qv[4] = {qa.x, qa.y, qa.z, qa.w};
                #pragma unroll
                for (int nn = 0; nn < 4; nn++) {
                    acc[nn].x = fmaf(qv[nn], wpx[j], acc[nn].x);
                    acc[nn].y = fmaf(qv[nn], wpy[j], acc[nn].y);
                }
                if (l == 0) {
                    #pragma unroll
                    for (int nn = 0; nn < 4; nn++)
                        acc64[nn] = fmaf(qv[nn], w64[j], acc64[nn]);
                }
            }
        }

        #pragma unroll
        for (int nn = 0; nn < 4; nn++) {
            *reinterpret_cast<float2*>(&sm[FPR + (w * 4 + nn) * 66 + 2 * l]) = acc[nn];
        }
        if (l == 0) {
            #pragma unroll
            for (int nn = 0; nn < 4; nn++) sm[FPR + (w * 4 + nn) * 66 + 64] = acc64[nn];
        }
        __syncthreads();

        for (int o = tid; o < 260; o += 256) {
            const int nn = o / 65;
            const int c  = o - nn * 65;
            float s = 0.f;
            #pragma unroll
            for (int w8 = 0; w8 < 8; w8++) s += sm[FPR + (w8 * 4 + nn) * 66 + c];
            sm[FSW + nn * 68 + c] = s + bg[c];
        }
    }
    __syncthreads();

    // ---- Build packed u64 tables + per-box LA ----
    {
        u64* stw10 = reinterpret_cast<u64*>(&sm[FTAB]);
        u64* stw2h = stw10 + 32;
        u64* stw1  = stw10 + 64;
        u64* stb1  = stw10 + 96;
        if (tid < 32) {
            const int nn = tid >> 3;
            const int k2 = tid & 7;
            const int k  = 2 * k2;
            const float* wv = &sm[FSW + nn * 68];
            const float h0 = 0.5f * wv[48 + k];
            const float h1 = 0.5f * wv[48 + k + 1];
            stw10[nn * 8 + k2] = pack2(wv[k], wv[k + 1]);
            stw2h[nn * 8 + k2] = pack2(h0, h1);
            stw1[nn * 8 + k2]  = pack2(wv[16 + k], wv[16 + k + 1]);
            stb1[nn * 8 + k2]  = pack2(wv[32 + k], wv[32 + k + 1]);
        } else if (tid < 36) {
            const int nn = tid - 32;
            const float* wv = &sm[FSW + nn * 68];
            float LA = 0.f;
            #pragma unroll
            for (int k = 0; k < 16; k++)
                LA = fmaf(wv[k], 0.5f * wv[48 + k], LA);
            sm[FLA + nn] = LA;
        }
    }
    __syncthreads();

    // ---- Phase 2: pixel evaluation ----
    const u64* stw10 = reinterpret_cast<const u64*>(&sm[FTAB]);
    const u64* stw2h = stw10 + 32;
    const u64* stw1  = stw10 + 64;
    const u64* stb1  = stw10 + 96;

    const int y  = tid >> 2;
    const int x0 = (tid & 3) * 16;
    const float yc = ((float)y + 0.5f) * (1.0f / 64.0f);

    for (int nn = 0; nn < 4; nn++) {
        const float4 p = spos[nn];
        const float inv_bw = 1.0f / p.z;
        const float inv_bh = 1.0f / p.w;
        const float rel_y = (yc - p.y) * inv_bh;

        // Per-thread ayp + LB (table reads are broadcast LDS.64)
        u64 ayp[8];
        float LB = 0.f;
        #pragma unroll
        for (int k2 = 0; k2 < 8; k2++) {
            float w1a, w1b, b1a, b1b, h0, h1;
            unpack2(stw1[nn * 8 + k2], w1a, w1b);
            unpack2(stb1[nn * 8 + k2], b1a, b1b);
            unpack2(stw2h[nn * 8 + k2], h0, h1);
            const float a0 = fmaf(rel_y, w1a, b1a);
            const float a1 = fmaf(rel_y, w1b, b1b);
            ayp[k2] = pack2(a0, a1);
            LB = fmaf(a0, h0, LB);
            LB = fmaf(a1, h1, LB);
        }
        const float LA   = sm[FLA + nn];
        const float LBb2 = LB + sm[FSW + nn * 68 + 64];

        const float sx = inv_bw * (1.0f / 64.0f);
        const float tx = (0.5f * (1.0f / 64.0f) - p.x) * inv_bw;

        float* orow = out + (((size_t)(n0 + nn) * 64 + y) * 64 + x0);

        #pragma unroll
        for (int batch = 0; batch < 2; batch++) {
            const int xb = x0 + batch * 8;

            u64 x2[8];
            #pragma unroll
            for (int j = 0; j < 8; j++) {
                const float r = fmaf((float)(xb + j), sx, tx);
                x2[j] = pack2(r, r);
            }

            u64 acc[8];
            {
                const u64 w10 = stw10[nn * 8];
                const u64 w2h = stw2h[nn * 8];
                #pragma unroll
                for (int j = 0; j < 8; j++)
                    fma2_abs_init(acc[j], x2[j], w10, ayp[0], w2h);
            }
            #pragma unroll
            for (int k2 = 1; k2 < 8; k2++) {
                const u64 w10 = stw10[nn * 8 + k2];
                const u64 w2h = stw2h[nn * 8 + k2];
                #pragma unroll
                for (int j = 0; j < 8; j++)
                    fma2_abs_acc(acc[j], x2[j], w10, ayp[k2], w2h);
            }

            float res[8];
            #pragma unroll
            for (int j = 0; j < 8; j++) {
                float lo, hi, rxv, rdum;
                unpack2(acc[j], lo, hi);
                unpack2(x2[j], rxv, rdum);
                res[j] = (lo + hi) + fmaf(rxv, LA, LBb2);
            }
            float4 v0 = make_float4(res[0], res[1], res[2], res[3]);
            float4 v1 = make_float4(res[4], res[5], res[6], res[7]);
            *reinterpret_cast<float4*>(orow + batch * 8)     = v0;
            *reinterpret_cast<float4*>(orow + batch * 8 + 4) = v1;
        }
    }
}

// ===========================================================================
// Fallback path (other shapes).
// ===========================================================================
__global__ void posmlp_gemm_kernel(const float* __restrict__ q,
                                   const float* __restrict__ Wg,
                                   const float* __restrict__ bg,
                                   float* __restrict__ w_out,
                                   int dim, int cols) {
    extern __shared__ float sqf[];
    const int n = blockIdx.x;
    const float* qr = q + (size_t)n * dim;
    for (int d = threadIdx.x; d < dim; d += blockDim.x) sqf[d] = qr[d];
    __syncthreads();
    for (int j = threadIdx.x; j < cols; j += blockDim.x) {
        float acc = bg[j];
        #pragma unroll 8
        for (int d = 0; d < dim; d++) {
            acc = fmaf(sqf[d], Wg[(size_t)d * cols + j], acc);
        }
        w_out[(size_t)n * cols + j] = acc;
    }
}

__global__ void posmlp_generic_kernel(const float* __restrict__ pos,
                                      const float* __restrict__ wts,
                                      float* __restrict__ out,
                                      int H, int W, int h, int cols) {
    const int n = blockIdx.x;
    const float* w = wts + (size_t)n * cols;
    const float cx = pos[(size_t)n * 4 + 0];
    const float cy = pos[(size_t)n * 4 + 1];
    const float bw = pos[(size_t)n * 4 + 2];
    const float bh = pos[(size_t)n * 4 + 3];
    const float b2 = w[4 * h];
    const int total = H * W;
    for (int idx = threadIdx.x; idx < total; idx += blockDim.x) {
        const int yy = idx / W;
        const int xx = idx - yy * W;
        const float rel_x = (((float)xx + 0.5f) / (float)W - cx) / bw;
        const float rel_y = (((float)yy + 0.5f) / (float)H - cy) / bh;
        float acc = b2;
        for (int k = 0; k < h; k++) {
            float pre = fmaf(rel_x, w[k], fmaf(rel_y, w[h + k], w[2 * h + k]));
            acc = fmaf(fmaxf(pre, 0.0f), w[3 * h + k], acc);
        }
        out[(size_t)n * total + idx] = acc;
    }
}

extern "C" void kernel_launch(void* const* d_in, const int* in_sizes, int n_in,
                              void* d_out, int out_size) {
    const float* pos = (const float*)d_in[0];
    const float* q   = (const float*)d_in[1];
    const float* Wg  = (const float*)d_in[2];
    const float* bg  = (const float*)d_in[3];
    float* out = (float*)d_out;

    const int N    = in_sizes[0] / 4;          // rows of pos
    const int dim  = in_sizes[1] / N;          // query dim
    const int cols = in_sizes[3];              // 4*h + 1
    const int HW   = out_size / N;
    const int H    = (int)(sqrt((double)HW) + 0.5);
    const int h    = (cols - 1) / 4;

    if (H == 64 && h == 16 && cols == 65 && dim == 256 && (N % 4) == 0) {
        const int smem_bytes = FTOT * sizeof(float);  // ~14.7 KB
        cudaFuncSetAttribute(posmlp_fused4_kernel,
                             cudaFuncAttributeMaxDynamicSharedMemorySize, smem_bytes);
        posmlp_fused4_kernel<<<N / 4, 256, smem_bytes>>>(pos, q, Wg, bg, out);
    } else {
        float* w_scratch;
        cudaGetSymbolAddress((void**)&w_scratch, g_weights);
        posmlp_gemm_kernel<<<N, 256, dim * sizeof(float)>>>(q, Wg, bg, w_scratch, dim, cols);
        posmlp_generic_kernel<<<N, 256>>>(pos, w_scratch, out, H, H, h, cols);
    }
}